// round 5
// baseline (speedup 1.0000x reference)
#include <cuda_runtime.h>
#include <math.h>

#define BB 2
#define SS 2048
#define EE 2048
#define HH 16
#define KVH 4
#define DD 128
#define GG (HH / KVH)

// ---------------- scratch (device globals; no allocations allowed) ----------------
__device__ float g_q_tmp[4096 * 2048];   // q proj, later reused for reshaped attn
__device__ float g_k_tmp[4096 * 512];
__device__ float g_v_tmp[4096 * 512];
__device__ float g_q[(size_t)BB * HH * SS * DD];
__device__ float g_k[(size_t)BB * KVH * SS * DD];
__device__ float g_v[(size_t)BB * KVH * SS * DD];
__device__ float g_attn[(size_t)BB * HH * SS * DD];

// ---------------- tiled fp32 GEMM: C[M,N] = A[M,K] @ B[K,N] ----------------
// BM=128, BN=64, BK=16, 256 threads, 8x4 microtile per thread.
#define GBM 128
#define GBN 64
#define GBK 16

__global__ __launch_bounds__(256) void gemm_kernel(
    const float* __restrict__ A, const float* __restrict__ Bm, float* __restrict__ C,
    int M, int N, int K)
{
    __shared__ float As[GBK][GBM + 4];   // transposed [k][m], pad 4 keeps float4 alignment
    __shared__ float Bs[GBK][GBN];

    int tid = threadIdx.x;
    int tx = tid & 15, ty = tid >> 4;
    int m0 = blockIdx.y * GBM;
    int n0 = blockIdx.x * GBN;

    float acc[8][4];
#pragma unroll
    for (int i = 0; i < 8; i++)
#pragma unroll
        for (int j = 0; j < 4; j++) acc[i][j] = 0.f;

    for (int k0 = 0; k0 < K; k0 += GBK) {
        // load A tile: 128x16 = 512 float4, 2 per thread
#pragma unroll
        for (int r = 0; r < 2; r++) {
            int f = tid + 256 * r;
            int m = f >> 2;
            int kc = (f & 3) * 4;
            float4 av = *(const float4*)(A + (size_t)(m0 + m) * K + k0 + kc);
            As[kc + 0][m] = av.x; As[kc + 1][m] = av.y;
            As[kc + 2][m] = av.z; As[kc + 3][m] = av.w;
        }
        // load B tile: 16x64 = 256 float4, 1 per thread
        {
            int kk = tid >> 4;
            int nc = (tid & 15) * 4;
            *(float4*)(&Bs[kk][nc]) = *(const float4*)(Bm + (size_t)(k0 + kk) * N + n0 + nc);
        }
        __syncthreads();
#pragma unroll
        for (int k = 0; k < GBK; k++) {
            float4 a0 = *(const float4*)(&As[k][ty * 8]);
            float4 a1 = *(const float4*)(&As[k][ty * 8 + 4]);
            float4 bv = *(const float4*)(&Bs[k][tx * 4]);
            float a[8] = {a0.x, a0.y, a0.z, a0.w, a1.x, a1.y, a1.z, a1.w};
            float bb[4] = {bv.x, bv.y, bv.z, bv.w};
#pragma unroll
            for (int i = 0; i < 8; i++)
#pragma unroll
                for (int j = 0; j < 4; j++) acc[i][j] += a[i] * bb[j];
        }
        __syncthreads();
    }
#pragma unroll
    for (int i = 0; i < 8; i++) {
        int m = m0 + ty * 8 + i;
        float4 v = make_float4(acc[i][0], acc[i][1], acc[i][2], acc[i][3]);
        *(float4*)(C + (size_t)m * N + n0 + tx * 4) = v;
    }
}

// ---------------- RoPE + reshape: [B*S, nh*D] -> [B, nh, S, D] ----------------
__global__ void rope_reshape_kernel(const float* __restrict__ src, float* __restrict__ dst, int nh)
{
    int idx = blockIdx.x * blockDim.x + threadIdx.x;
    int total = BB * nh * SS * DD;
    if (idx >= total) return;
    int d = idx & (DD - 1);
    int s = (idx >> 7) & (SS - 1);
    int hb = idx >> 18;          // D*S = 2^18
    int h = hb % nh;
    int b = hb / nh;
    const float* row = src + ((size_t)(b * SS + s)) * nh * DD + h * DD;
    float x = row[d];
    int j = d & 63;
    // inv_freq = 10000^(-j/64) computed as exp(-j*ln(10000)/64), matches fp32 ref closely
    float invf = expf(-(float)j * (9.210340371976184f / 64.f));
    float phase = (float)s * invf;
    float sn, cs;
    sincosf(phase, &sn, &cs);
    float xp = (d < 64) ? -row[d + 64] : row[d - 64];
    dst[idx] = x * cs + xp * sn;
}

// ---------------- reshape V: [B*S, KV*D] -> [B, KV, S, D] ----------------
__global__ void reshape_v_kernel(const float* __restrict__ src, float* __restrict__ dst)
{
    int idx = blockIdx.x * blockDim.x + threadIdx.x;
    int total = BB * KVH * SS * DD;
    if (idx >= total) return;
    int d = idx & (DD - 1);
    int s = (idx >> 7) & (SS - 1);
    int hb = idx >> 18;
    int h = hb % KVH;
    int b = hb / KVH;
    dst[idx] = src[((size_t)(b * SS + s)) * KVH * DD + h * DD + d];
}

// ---------------- reshape attn: [B,H,S,D] -> [B*S, H*D] ----------------
__global__ void reshape_attn_kernel(const float* __restrict__ src, float* __restrict__ dst)
{
    int idx = blockIdx.x * blockDim.x + threadIdx.x;
    int total = BB * SS * HH * DD;
    if (idx >= total) return;
    int c = idx & (HH * DD - 1);   // 2048 = 2^11
    int r = idx >> 11;
    int h = c >> 7, d = c & 127;
    int b = r >> 11, s = r & 2047;
    dst[idx] = src[(((size_t)(b * HH + h)) * SS + s) * DD + d];
}

// ---------------- flash attention (causal, GQA) ----------------
// Per CTA: one (b,h) head, one 64-row query tile. 256 threads (16x16), 4x4 S-microtile,
// 4x8 O-microtile. K and V share one smem buffer. Online softmax.
#define AT_BM 64
#define AT_BN 64
#define QS_STRIDE 68
#define VS_STRIDE 132
#define ATT_SMEM ((128 * 68 * 2 + 64 * 68) * 4)

__global__ __launch_bounds__(256) void attn_kernel(
    const float* __restrict__ Q, const float* __restrict__ K, const float* __restrict__ V,
    float* __restrict__ O)
{
    extern __shared__ float sm[];
    float* Qs = sm;                   // [d][m], stride 68
    float* KVs = sm + 128 * 68;       // K: [d][n] stride 68 | V: [n][dd] stride 132
    float* Ps = sm + 2 * 128 * 68;    // [m][n], stride 68

    int tid = threadIdx.x;
    int tx = tid & 15, ty = tid >> 4;
    int head = blockIdx.y;
    int b = head / HH, h = head % HH;
    int kv = h / GG;
    int qt = blockIdx.x;
    int m0 = qt * AT_BM;

    const float* Qg = Q + ((size_t)(b * HH + h)) * SS * DD;
    const float* Kg = K + ((size_t)(b * KVH + kv)) * SS * DD;
    const float* Vg = V + ((size_t)(b * KVH + kv)) * SS * DD;

    // load Q tile [64][128] transposed into Qs[d][m]
#pragma unroll
    for (int r = 0; r < 8; r++) {
        int f = tid + 256 * r;
        int m = f >> 5;
        int dc = (f & 31) * 4;
        float4 v = *(const float4*)(Qg + (size_t)(m0 + m) * DD + dc);
        Qs[(dc + 0) * QS_STRIDE + m] = v.x;
        Qs[(dc + 1) * QS_STRIDE + m] = v.y;
        Qs[(dc + 2) * QS_STRIDE + m] = v.z;
        Qs[(dc + 3) * QS_STRIDE + m] = v.w;
    }

    float m_run[4], l_run[4], Oa[4][8];
#pragma unroll
    for (int i = 0; i < 4; i++) {
        m_run[i] = -1e30f; l_run[i] = 0.f;
#pragma unroll
        for (int j = 0; j < 8; j++) Oa[i][j] = 0.f;
    }
    const float scale = 0.08838834764831845f;   // 1/sqrt(128)

    for (int kt = 0; kt <= qt; kt++) {
        int c0 = kt * AT_BN;
        __syncthreads();   // prev iter done with KVs(V); also makes Qs visible on iter 0
        // load K tile [64][128] transposed into KVs[d][n]
#pragma unroll
        for (int r = 0; r < 8; r++) {
            int f = tid + 256 * r;
            int n = f >> 5;
            int dc = (f & 31) * 4;
            float4 v = *(const float4*)(Kg + (size_t)(c0 + n) * DD + dc);
            KVs[(dc + 0) * QS_STRIDE + n] = v.x;
            KVs[(dc + 1) * QS_STRIDE + n] = v.y;
            KVs[(dc + 2) * QS_STRIDE + n] = v.z;
            KVs[(dc + 3) * QS_STRIDE + n] = v.w;
        }
        __syncthreads();

        // S = scale * Q K^T   (4x4 microtile per thread)
        float sacc[4][4];
#pragma unroll
        for (int i = 0; i < 4; i++)
#pragma unroll
            for (int j = 0; j < 4; j++) sacc[i][j] = 0.f;
#pragma unroll 8
        for (int d = 0; d < 128; d++) {
            float4 qv = *(const float4*)(&Qs[d * QS_STRIDE + ty * 4]);
            float4 kv4 = *(const float4*)(&KVs[d * QS_STRIDE + tx * 4]);
            float qa[4] = {qv.x, qv.y, qv.z, qv.w};
            float ka[4] = {kv4.x, kv4.y, kv4.z, kv4.w};
#pragma unroll
            for (int i = 0; i < 4; i++)
#pragma unroll
                for (int j = 0; j < 4; j++) sacc[i][j] += qa[i] * ka[j];
        }
#pragma unroll
        for (int i = 0; i < 4; i++)
#pragma unroll
            for (int j = 0; j < 4; j++) sacc[i][j] *= scale;

        if (kt == qt) {   // diagonal tile: causal mask (m0 == c0)
#pragma unroll
            for (int i = 0; i < 4; i++)
#pragma unroll
                for (int j = 0; j < 4; j++)
                    if (tx * 4 + j > ty * 4 + i) sacc[i][j] = -INFINITY;
        }

        // online softmax per row (16 lanes share a row group)
#pragma unroll
        for (int i = 0; i < 4; i++) {
            float mx = fmaxf(fmaxf(sacc[i][0], sacc[i][1]), fmaxf(sacc[i][2], sacc[i][3]));
#pragma unroll
            for (int off = 8; off > 0; off >>= 1)
                mx = fmaxf(mx, __shfl_xor_sync(0xffffffffu, mx, off, 16));
            float mnew = fmaxf(m_run[i], mx);
            float alpha = expf(m_run[i] - mnew);
            float rs = 0.f;
#pragma unroll
            for (int j = 0; j < 4; j++) {
                float p = expf(sacc[i][j] - mnew);
                sacc[i][j] = p;
                rs += p;
            }
#pragma unroll
            for (int off = 8; off > 0; off >>= 1)
                rs += __shfl_xor_sync(0xffffffffu, rs, off, 16);
            l_run[i] = l_run[i] * alpha + rs;
            m_run[i] = mnew;
#pragma unroll
            for (int j = 0; j < 8; j++) Oa[i][j] *= alpha;
        }

        // store P[m][n]
#pragma unroll
        for (int i = 0; i < 4; i++)
            *(float4*)(&Ps[(ty * 4 + i) * QS_STRIDE + tx * 4]) =
                make_float4(sacc[i][0], sacc[i][1], sacc[i][2], sacc[i][3]);
        __syncthreads();   // P visible; all done reading K

        // load V tile [64][128] into KVs[n][dd]
#pragma unroll
        for (int r = 0; r < 8; r++) {
            int f = tid + 256 * r;
            int n = f >> 5;
            int dc = (f & 31) * 4;
            *(float4*)(&KVs[n * VS_STRIDE + dc]) =
                *(const float4*)(Vg + (size_t)(c0 + n) * DD + dc);
        }
        __syncthreads();

        // O += P @ V
#pragma unroll 8
        for (int n = 0; n < 64; n++) {
            float p0 = Ps[(ty * 4 + 0) * QS_STRIDE + n];
            float p1 = Ps[(ty * 4 + 1) * QS_STRIDE + n];
            float p2 = Ps[(ty * 4 + 2) * QS_STRIDE + n];
            float p3 = Ps[(ty * 4 + 3) * QS_STRIDE + n];
            float4 v0 = *(const float4*)(&KVs[n * VS_STRIDE + tx * 8]);
            float4 v1 = *(const float4*)(&KVs[n * VS_STRIDE + tx * 8 + 4]);
            float vv[8] = {v0.x, v0.y, v0.z, v0.w, v1.x, v1.y, v1.z, v1.w};
#pragma unroll
            for (int j = 0; j < 8; j++) {
                Oa[0][j] += p0 * vv[j];
                Oa[1][j] += p1 * vv[j];
                Oa[2][j] += p2 * vv[j];
                Oa[3][j] += p3 * vv[j];
            }
        }
    }

    float* Og = O + ((size_t)(b * HH + h)) * SS * DD;
#pragma unroll
    for (int i = 0; i < 4; i++) {
        float inv = 1.f / l_run[i];
        float4 o0 = make_float4(Oa[i][0] * inv, Oa[i][1] * inv, Oa[i][2] * inv, Oa[i][3] * inv);
        float4 o1 = make_float4(Oa[i][4] * inv, Oa[i][5] * inv, Oa[i][6] * inv, Oa[i][7] * inv);
        size_t base = (size_t)(m0 + ty * 4 + i) * DD + tx * 8;
        *(float4*)(Og + base) = o0;
        *(float4*)(Og + base + 4) = o1;
    }
}

// ---------------- launcher ----------------
extern "C" void kernel_launch(void* const* d_in, const int* in_sizes, int n_in,
                              void* d_out, int out_size)
{
    const float* x  = (const float*)d_in[0];
    const float* Wq = (const float*)d_in[1];
    const float* Wk = (const float*)d_in[2];
    const float* Wv = (const float*)d_in[3];
    const float* Wo = (const float*)d_in[4];
    float* out = (float*)d_out;

    float *qt, *ktm, *vtm, *q, *k, *v, *attn;
    cudaGetSymbolAddress((void**)&qt,  g_q_tmp);
    cudaGetSymbolAddress((void**)&ktm, g_k_tmp);
    cudaGetSymbolAddress((void**)&vtm, g_v_tmp);
    cudaGetSymbolAddress((void**)&q,   g_q);
    cudaGetSymbolAddress((void**)&k,   g_k);
    cudaGetSymbolAddress((void**)&v,   g_v);
    cudaGetSymbolAddress((void**)&attn, g_attn);

    const int M = BB * SS;            // 4096

    // QKV projections
    gemm_kernel<<<dim3(EE / GBN, M / GBM), 256>>>(x, Wq, qt,  M, HH * DD, EE);
    gemm_kernel<<<dim3((KVH * DD) / GBN, M / GBM), 256>>>(x, Wk, ktm, M, KVH * DD, EE);
    gemm_kernel<<<dim3((KVH * DD) / GBN, M / GBM), 256>>>(x, Wv, vtm, M, KVH * DD, EE);

    // RoPE + layout transforms
    {
        int nq = BB * HH * SS * DD;
        rope_reshape_kernel<<<(nq + 255) / 256, 256>>>(qt, q, HH);
        int nk = BB * KVH * SS * DD;
        rope_reshape_kernel<<<(nk + 255) / 256, 256>>>(ktm, k, KVH);
        reshape_v_kernel<<<(nk + 255) / 256, 256>>>(vtm, v);
    }

    // attention
    cudaFuncSetAttribute(attn_kernel, cudaFuncAttributeMaxDynamicSharedMemorySize, ATT_SMEM);
    attn_kernel<<<dim3(SS / AT_BM, BB * HH), 256, ATT_SMEM>>>(q, k, v, attn);

    // reshape + output projection (reuse qt as scratch)
    {
        int na = BB * SS * HH * DD;
        reshape_attn_kernel<<<(na + 255) / 256, 256>>>(attn, qt);
    }
    gemm_kernel<<<dim3(EE / GBN, M / GBM), 256>>>(qt, Wo, out, M, EE, EE);
}

// round 9
// speedup vs baseline: 1.4729x; 1.4729x over previous
#include <cuda_runtime.h>
#include <math.h>

#define BB 2
#define SS 2048
#define EE 2048
#define HH 16
#define KVH 4
#define DD 128
#define GG (HH / KVH)

// ---------------- scratch (device globals; no allocations allowed) ----------------
__device__ float g_q_tmp[4096 * 2048];   // q proj, later reused for reshaped attn
__device__ float g_k_tmp[4096 * 512];
__device__ float g_v_tmp[4096 * 512];
__device__ float g_q[(size_t)BB * HH * SS * DD];
__device__ float g_k[(size_t)BB * KVH * SS * DD];
__device__ float g_v[(size_t)BB * KVH * SS * DD];
__device__ float g_attn[(size_t)BB * HH * SS * DD];

// ================= TF32 tensor-core GEMM: C[M,N] = A[M,K] @ B[K,N] =================
// 128x128 CTA tile, BK=16, 256 threads = 8 warps in 2x4 grid of 64x32 warp tiles.
// mma.sync.aligned.m16n8k8.row.col.f32.tf32.tf32.f32
#define TBM 128
#define TBN 128
#define TBK 16
#define AS_STRIDE 20    // floats; banks verified conflict-free for all fragment reads
#define BS_STRIDE 136   // floats; stride mod 32 == 8 -> 32 distinct banks

__device__ __forceinline__ unsigned f2tf32(float f) {
    unsigned r;
    asm("cvt.rna.tf32.f32 %0, %1;" : "=r"(r) : "f"(f));
    return r;
}

__device__ __forceinline__ void mma_tf32(float c[4], const unsigned a[4], const unsigned b[2]) {
    asm volatile(
        "mma.sync.aligned.m16n8k8.row.col.f32.tf32.tf32.f32 "
        "{%0,%1,%2,%3}, {%4,%5,%6,%7}, {%8,%9}, {%0,%1,%2,%3};\n"
        : "+f"(c[0]), "+f"(c[1]), "+f"(c[2]), "+f"(c[3])
        : "r"(a[0]), "r"(a[1]), "r"(a[2]), "r"(a[3]), "r"(b[0]), "r"(b[1]));
}

__global__ __launch_bounds__(256) void gemm_tf32_kernel(
    const float* __restrict__ A, const float* __restrict__ Bm, float* __restrict__ C,
    int M, int N, int K)
{
    __shared__ float As[TBM * AS_STRIDE];   // [m][k]
    __shared__ float Bs[TBK * BS_STRIDE];   // [k][n]

    int tid = threadIdx.x;
    int lane = tid & 31;
    int warp = tid >> 5;
    int gid = lane >> 2;      // group id (0..7)
    int tig = lane & 3;       // thread in group (0..3)
    int warp_m = warp >> 2;   // 0..1
    int warp_n = warp & 3;    // 0..3

    int m0 = blockIdx.y * TBM;
    int n0 = blockIdx.x * TBN;

    float acc[4][4][4];
#pragma unroll
    for (int i = 0; i < 4; i++)
#pragma unroll
        for (int j = 0; j < 4; j++)
#pragma unroll
            for (int r = 0; r < 4; r++) acc[i][j][r] = 0.f;

    for (int k0 = 0; k0 < K; k0 += TBK) {
        // ---- load A tile 128x16: 512 float4, 2 per thread ----
#pragma unroll
        for (int r = 0; r < 2; r++) {
            int f = tid + 256 * r;
            int m = f >> 2;
            int kc = (f & 3) * 4;
            float4 av = *(const float4*)(A + (size_t)(m0 + m) * K + k0 + kc);
            float* dst = &As[m * AS_STRIDE + kc];
            dst[0] = __uint_as_float(f2tf32(av.x));
            dst[1] = __uint_as_float(f2tf32(av.y));
            dst[2] = __uint_as_float(f2tf32(av.z));
            dst[3] = __uint_as_float(f2tf32(av.w));
        }
        // ---- load B tile 16x128: 512 float4, 2 per thread ----
#pragma unroll
        for (int r = 0; r < 2; r++) {
            int f = tid + 256 * r;
            int kk = f >> 5;
            int nc = (f & 31) * 4;
            float4 bv = *(const float4*)(Bm + (size_t)(k0 + kk) * N + n0 + nc);
            float4 tv;
            tv.x = __uint_as_float(f2tf32(bv.x));
            tv.y = __uint_as_float(f2tf32(bv.y));
            tv.z = __uint_as_float(f2tf32(bv.z));
            tv.w = __uint_as_float(f2tf32(bv.w));
            *(float4*)(&Bs[kk * BS_STRIDE + nc]) = tv;
        }
        __syncthreads();

#pragma unroll
        for (int kk = 0; kk < TBK; kk += 8) {
            // A fragments: 4 per warp (64 rows)
            unsigned afrag[4][4];
#pragma unroll
            for (int am = 0; am < 4; am++) {
                int rm = warp_m * 64 + am * 16;
                const float* base = &As[(rm + gid) * AS_STRIDE + kk + tig];
                afrag[am][0] = __float_as_uint(base[0]);
                afrag[am][1] = __float_as_uint(base[8 * AS_STRIDE]);
                afrag[am][2] = __float_as_uint(base[4]);
                afrag[am][3] = __float_as_uint(base[8 * AS_STRIDE + 4]);
            }
            // B fragments: 4 per warp (32 cols)
            unsigned bfrag[4][2];
#pragma unroll
            for (int bn = 0; bn < 4; bn++) {
                int cn = warp_n * 32 + bn * 8 + gid;
                const float* base = &Bs[(kk + tig) * BS_STRIDE + cn];
                bfrag[bn][0] = __float_as_uint(base[0]);
                bfrag[bn][1] = __float_as_uint(base[4 * BS_STRIDE]);
            }
#pragma unroll
            for (int am = 0; am < 4; am++)
#pragma unroll
                for (int bn = 0; bn < 4; bn++)
                    mma_tf32(acc[am][bn], afrag[am], bfrag[bn]);
        }
        __syncthreads();
    }

    // ---- epilogue ----
#pragma unroll
    for (int am = 0; am < 4; am++) {
#pragma unroll
        for (int bn = 0; bn < 4; bn++) {
            int row = m0 + warp_m * 64 + am * 16 + gid;
            int col = n0 + warp_n * 32 + bn * 8 + 2 * tig;
            *(float2*)(C + (size_t)row * N + col) = make_float2(acc[am][bn][0], acc[am][bn][1]);
            *(float2*)(C + (size_t)(row + 8) * N + col) = make_float2(acc[am][bn][2], acc[am][bn][3]);
        }
    }
}

// ---------------- RoPE + reshape: [B*S, nh*D] -> [B, nh, S, D] ----------------
__global__ void rope_reshape_kernel(const float* __restrict__ src, float* __restrict__ dst, int nh)
{
    int idx = blockIdx.x * blockDim.x + threadIdx.x;
    int total = BB * nh * SS * DD;
    if (idx >= total) return;
    int d = idx & (DD - 1);
    int s = (idx >> 7) & (SS - 1);
    int hb = idx >> 18;          // D*S = 2^18
    int h = hb % nh;
    int b = hb / nh;
    const float* row = src + ((size_t)(b * SS + s)) * nh * DD + h * DD;
    float x = row[d];
    int j = d & 63;
    float invf = expf(-(float)j * (9.210340371976184f / 64.f));
    float phase = (float)s * invf;
    float sn, cs;
    sincosf(phase, &sn, &cs);
    float xp = (d < 64) ? -row[d + 64] : row[d - 64];
    dst[idx] = x * cs + xp * sn;
}

// ---------------- reshape V: [B*S, KV*D] -> [B, KV, S, D] ----------------
__global__ void reshape_v_kernel(const float* __restrict__ src, float* __restrict__ dst)
{
    int idx = blockIdx.x * blockDim.x + threadIdx.x;
    int total = BB * KVH * SS * DD;
    if (idx >= total) return;
    int d = idx & (DD - 1);
    int s = (idx >> 7) & (SS - 1);
    int hb = idx >> 18;
    int h = hb % KVH;
    int b = hb / KVH;
    dst[idx] = src[((size_t)(b * SS + s)) * KVH * DD + h * DD + d];
}

// ---------------- reshape attn: [B,H,S,D] -> [B*S, H*D] ----------------
__global__ void reshape_attn_kernel(const float* __restrict__ src, float* __restrict__ dst)
{
    int idx = blockIdx.x * blockDim.x + threadIdx.x;
    int total = BB * SS * HH * DD;
    if (idx >= total) return;
    int c = idx & (HH * DD - 1);   // 2048 = 2^11
    int r = idx >> 11;
    int h = c >> 7, d = c & 127;
    int b = r >> 11, s = r & 2047;
    dst[idx] = src[(((size_t)(b * HH + h)) * SS + s) * DD + d];
}

// ---------------- flash attention (causal, GQA) ----------------
#define AT_BM 64
#define AT_BN 64
#define QS_STRIDE 68
#define VS_STRIDE 132
#define ATT_SMEM ((128 * 68 * 2 + 64 * 68) * 4)

__global__ __launch_bounds__(256) void attn_kernel(
    const float* __restrict__ Q, const float* __restrict__ K, const float* __restrict__ V,
    float* __restrict__ O)
{
    extern __shared__ float sm[];
    float* Qs = sm;                   // [d][m], stride 68
    float* KVs = sm + 128 * 68;       // K: [d][n] stride 68 | V: [n][dd] stride 132
    float* Ps = sm + 2 * 128 * 68;    // [m][n], stride 68

    int tid = threadIdx.x;
    int tx = tid & 15, ty = tid >> 4;
    int head = blockIdx.y;
    int b = head / HH, h = head % HH;
    int kv = h / GG;
    int qt = blockIdx.x;
    int m0 = qt * AT_BM;

    const float* Qg = Q + ((size_t)(b * HH + h)) * SS * DD;
    const float* Kg = K + ((size_t)(b * KVH + kv)) * SS * DD;
    const float* Vg = V + ((size_t)(b * KVH + kv)) * SS * DD;

#pragma unroll
    for (int r = 0; r < 8; r++) {
        int f = tid + 256 * r;
        int m = f >> 5;
        int dc = (f & 31) * 4;
        float4 v = *(const float4*)(Qg + (size_t)(m0 + m) * DD + dc);
        Qs[(dc + 0) * QS_STRIDE + m] = v.x;
        Qs[(dc + 1) * QS_STRIDE + m] = v.y;
        Qs[(dc + 2) * QS_STRIDE + m] = v.z;
        Qs[(dc + 3) * QS_STRIDE + m] = v.w;
    }

    float m_run[4], l_run[4], Oa[4][8];
#pragma unroll
    for (int i = 0; i < 4; i++) {
        m_run[i] = -1e30f; l_run[i] = 0.f;
#pragma unroll
        for (int j = 0; j < 8; j++) Oa[i][j] = 0.f;
    }
    const float scale = 0.08838834764831845f;   // 1/sqrt(128)

    for (int kt = 0; kt <= qt; kt++) {
        int c0 = kt * AT_BN;
        __syncthreads();
#pragma unroll
        for (int r = 0; r < 8; r++) {
            int f = tid + 256 * r;
            int n = f >> 5;
            int dc = (f & 31) * 4;
            float4 v = *(const float4*)(Kg + (size_t)(c0 + n) * DD + dc);
            KVs[(dc + 0) * QS_STRIDE + n] = v.x;
            KVs[(dc + 1) * QS_STRIDE + n] = v.y;
            KVs[(dc + 2) * QS_STRIDE + n] = v.z;
            KVs[(dc + 3) * QS_STRIDE + n] = v.w;
        }
        __syncthreads();

        float sacc[4][4];
#pragma unroll
        for (int i = 0; i < 4; i++)
#pragma unroll
            for (int j = 0; j < 4; j++) sacc[i][j] = 0.f;
#pragma unroll 8
        for (int d = 0; d < 128; d++) {
            float4 qv = *(const float4*)(&Qs[d * QS_STRIDE + ty * 4]);
            float4 kv4 = *(const float4*)(&KVs[d * QS_STRIDE + tx * 4]);
            float qa[4] = {qv.x, qv.y, qv.z, qv.w};
            float ka[4] = {kv4.x, kv4.y, kv4.z, kv4.w};
#pragma unroll
            for (int i = 0; i < 4; i++)
#pragma unroll
                for (int j = 0; j < 4; j++) sacc[i][j] += qa[i] * ka[j];
        }
#pragma unroll
        for (int i = 0; i < 4; i++)
#pragma unroll
            for (int j = 0; j < 4; j++) sacc[i][j] *= scale;

        if (kt == qt) {
#pragma unroll
            for (int i = 0; i < 4; i++)
#pragma unroll
                for (int j = 0; j < 4; j++)
                    if (tx * 4 + j > ty * 4 + i) sacc[i][j] = -INFINITY;
        }

#pragma unroll
        for (int i = 0; i < 4; i++) {
            float mx = fmaxf(fmaxf(sacc[i][0], sacc[i][1]), fmaxf(sacc[i][2], sacc[i][3]));
#pragma unroll
            for (int off = 8; off > 0; off >>= 1)
                mx = fmaxf(mx, __shfl_xor_sync(0xffffffffu, mx, off, 16));
            float mnew = fmaxf(m_run[i], mx);
            float alpha = expf(m_run[i] - mnew);
            float rs = 0.f;
#pragma unroll
            for (int j = 0; j < 4; j++) {
                float p = expf(sacc[i][j] - mnew);
                sacc[i][j] = p;
                rs += p;
            }
#pragma unroll
            for (int off = 8; off > 0; off >>= 1)
                rs += __shfl_xor_sync(0xffffffffu, rs, off, 16);
            l_run[i] = l_run[i] * alpha + rs;
            m_run[i] = mnew;
#pragma unroll
            for (int j = 0; j < 8; j++) Oa[i][j] *= alpha;
        }

#pragma unroll
        for (int i = 0; i < 4; i++)
            *(float4*)(&Ps[(ty * 4 + i) * QS_STRIDE + tx * 4]) =
                make_float4(sacc[i][0], sacc[i][1], sacc[i][2], sacc[i][3]);
        __syncthreads();

#pragma unroll
        for (int r = 0; r < 8; r++) {
            int f = tid + 256 * r;
            int n = f >> 5;
            int dc = (f & 31) * 4;
            *(float4*)(&KVs[n * VS_STRIDE + dc]) =
                *(const float4*)(Vg + (size_t)(c0 + n) * DD + dc);
        }
        __syncthreads();

#pragma unroll 8
        for (int n = 0; n < 64; n++) {
            float p0 = Ps[(ty * 4 + 0) * QS_STRIDE + n];
            float p1 = Ps[(ty * 4 + 1) * QS_STRIDE + n];
            float p2 = Ps[(ty * 4 + 2) * QS_STRIDE + n];
            float p3 = Ps[(ty * 4 + 3) * QS_STRIDE + n];
            float4 v0 = *(const float4*)(&KVs[n * VS_STRIDE + tx * 8]);
            float4 v1 = *(const float4*)(&KVs[n * VS_STRIDE + tx * 8 + 4]);
            float vv[8] = {v0.x, v0.y, v0.z, v0.w, v1.x, v1.y, v1.z, v1.w};
#pragma unroll
            for (int j = 0; j < 8; j++) {
                Oa[0][j] += p0 * vv[j];
                Oa[1][j] += p1 * vv[j];
                Oa[2][j] += p2 * vv[j];
                Oa[3][j] += p3 * vv[j];
            }
        }
    }

    float* Og = O + ((size_t)(b * HH + h)) * SS * DD;
#pragma unroll
    for (int i = 0; i < 4; i++) {
        float inv = 1.f / l_run[i];
        float4 o0 = make_float4(Oa[i][0] * inv, Oa[i][1] * inv, Oa[i][2] * inv, Oa[i][3] * inv);
        float4 o1 = make_float4(Oa[i][4] * inv, Oa[i][5] * inv, Oa[i][6] * inv, Oa[i][7] * inv);
        size_t base = (size_t)(m0 + ty * 4 + i) * DD + tx * 8;
        *(float4*)(Og + base) = o0;
        *(float4*)(Og + base + 4) = o1;
    }
}

// ---------------- launcher ----------------
extern "C" void kernel_launch(void* const* d_in, const int* in_sizes, int n_in,
                              void* d_out, int out_size)
{
    const float* x  = (const float*)d_in[0];
    const float* Wq = (const float*)d_in[1];
    const float* Wk = (const float*)d_in[2];
    const float* Wv = (const float*)d_in[3];
    const float* Wo = (const float*)d_in[4];
    float* out = (float*)d_out;

    float *qt, *ktm, *vtm, *q, *k, *v, *attn;
    cudaGetSymbolAddress((void**)&qt,  g_q_tmp);
    cudaGetSymbolAddress((void**)&ktm, g_k_tmp);
    cudaGetSymbolAddress((void**)&vtm, g_v_tmp);
    cudaGetSymbolAddress((void**)&q,   g_q);
    cudaGetSymbolAddress((void**)&k,   g_k);
    cudaGetSymbolAddress((void**)&v,   g_v);
    cudaGetSymbolAddress((void**)&attn, g_attn);

    const int M = BB * SS;            // 4096

    // QKV projections (TF32 tensor cores)
    gemm_tf32_kernel<<<dim3((HH * DD) / TBN, M / TBM), 256>>>(x, Wq, qt,  M, HH * DD, EE);
    gemm_tf32_kernel<<<dim3((KVH * DD) / TBN, M / TBM), 256>>>(x, Wk, ktm, M, KVH * DD, EE);
    gemm_tf32_kernel<<<dim3((KVH * DD) / TBN, M / TBM), 256>>>(x, Wv, vtm, M, KVH * DD, EE);

    // RoPE + layout transforms
    {
        int nq = BB * HH * SS * DD;
        rope_reshape_kernel<<<(nq + 255) / 256, 256>>>(qt, q, HH);
        int nk = BB * KVH * SS * DD;
        rope_reshape_kernel<<<(nk + 255) / 256, 256>>>(ktm, k, KVH);
        reshape_v_kernel<<<(nk + 255) / 256, 256>>>(vtm, v);
    }

    // attention
    cudaFuncSetAttribute(attn_kernel, cudaFuncAttributeMaxDynamicSharedMemorySize, ATT_SMEM);
    attn_kernel<<<dim3(SS / AT_BM, BB * HH), 256, ATT_SMEM>>>(q, k, v, attn);

    // reshape + output projection (reuse qt as scratch)
    {
        int na = BB * SS * HH * DD;
        reshape_attn_kernel<<<(na + 255) / 256, 256>>>(attn, qt);
    }
    gemm_tf32_kernel<<<dim3(EE / TBN, M / TBM), 256>>>(qt, Wo, out, M, EE, EE);
}